// round 16
// baseline (speedup 1.0000x reference)
#include <cuda_runtime.h>

// Problem constants: B=4, M=8, N=128, D=32, 2D=64, H=64. BM = B*M = 32 sets.
#define NSET 32
#define NN   128
#define DD   32
#define DD2  64

// Padded strides: 17 float4 = 272 B row stride => 4-bank skew, conflict-free.
#define A1S_STRIDE4 17
#define DS_STRIDE   68

typedef unsigned long long u64;

// Scratch (device globals -- no allocation allowed)
__device__ float g_x1[NSET * NN * DD];
__device__ float g_A1[NSET * NN * DD2];
__device__ float g_A2[NSET * NN * DD2];
__device__ float g_mask[NSET * NN];
__device__ int   g_nv[NSET];               // valid prefix length per set

// ---------------- packed f32x2 helpers (sm_103a) ----------------
__device__ __forceinline__ u64 f2add(u64 a, u64 b) {
    u64 r; asm("add.rn.f32x2 %0,%1,%2;" : "=l"(r) : "l"(a), "l"(b)); return r;
}
__device__ __forceinline__ u64 f2mul(u64 a, u64 b) {
    u64 r; asm("mul.rn.f32x2 %0,%1,%2;" : "=l"(r) : "l"(a), "l"(b)); return r;
}
__device__ __forceinline__ u64 f2fma(u64 a, u64 b, u64 c) {
    u64 r; asm("fma.rn.f32x2 %0,%1,%2,%3;" : "=l"(r) : "l"(a), "l"(b), "l"(c)); return r;
}
__device__ __forceinline__ u64 f2pack(float lo, float hi) {
    u64 r; asm("mov.b64 %0,{%1,%2};" : "=l"(r) : "f"(lo), "f"(hi)); return r;
}
__device__ __forceinline__ void f2unpack(float& lo, float& hi, u64 v) {
    asm("mov.b64 {%0,%1},%2;" : "=f"(lo), "=f"(hi) : "l"(v));
}
__device__ __forceinline__ float tanh_ap(float x) {
    float r; asm("tanh.approx.f32 %0,%1;" : "=f"(r) : "f"(x)); return r;
}

// scalar gelu (jax tanh form) via tanh.approx.
__device__ __forceinline__ float gelu_f(float t) {
    float u  = t * t;
    float z  = t * fmaf(0.0356774081f, u, 0.7978845608f);
    float th = tanh_ap(z);
    float ht = 0.5f * t;
    return fmaf(th, ht, ht);
}

// Nonlinear part of gelu-dot, both packed lanes into ONE scalar accumulator
// (halves register pressure vs separate lo/hi accs). Linear term factored out.
__device__ __forceinline__ void gelu2_nl1(u64 a, u64 d, u64 hv, float& acc,
                                          u64 C1, u64 C2) {
    u64 t = f2add(a, d);
    u64 u = f2mul(t, t);
    u64 p = f2fma(C1, u, C2);
    u64 z = f2mul(t, p);
    u64 w = f2mul(t, hv);
    float zl, zh; f2unpack(zl, zh, z);
    float wl, wh; f2unpack(wl, wh, w);
    acc = fmaf(tanh_ap(zl), wl, acc);
    acc = fmaf(tanh_ap(zh), wh, acc);
}

// ---------------------------------------------------------------------------
// Kernel 1: per-set norm stats + set_norm + MLP1 + A1/A2 precompute + Nv.
// grid = NSET * 8 blocks (one set x 16 rows each), 256 threads.
// GEMM phases register-blocked 1x4 with LDS.128 weight loads.
// ---------------------------------------------------------------------------
__global__ __launch_bounds__(256) void k1(
    const float* __restrict__ x, const float* __restrict__ x_size,
    const float* __restrict__ W1a, const float* __restrict__ b1a,
    const float* __restrict__ W1b, const float* __restrict__ b1b,
    const float* __restrict__ W2a)
{
    __shared__ float xs[NN * DD];           // staging; later hb (1024) + x1b (512)
    __shared__ float w1a[DD * DD2];
    __shared__ float w1b[DD2 * DD];
    __shared__ float w2a[DD * DD2];
    __shared__ float xn[16 * DD];
    __shared__ float maskS[NN];
    __shared__ float red[8];
    __shared__ float statS[2];

    const int bm   = blockIdx.x >> 3;
    const int tile = blockIdx.x & 7;
    const int r0   = tile * 16;
    const int tid  = threadIdx.x;

    const float4* xg  = (const float4*)(x + bm * (NN * DD));
    float4*       xs4 = (float4*)xs;
    float lsum = 0.f;
    #pragma unroll
    for (int i = tid; i < 1024; i += 256) {
        float4 v = xg[i];
        xs4[i] = v;
        lsum += v.x + v.y + v.z + v.w;
    }
    #pragma unroll
    for (int i = tid; i < 512; i += 256) ((float4*)w1a)[i] = ((const float4*)W1a)[i];
    #pragma unroll
    for (int i = tid; i < 512; i += 256) ((float4*)w1b)[i] = ((const float4*)W1b)[i];
    #pragma unroll
    for (int i = tid; i < 512; i += 256) ((float4*)w2a)[i] = ((const float4*)W2a)[i];
    __syncthreads();

    if (tid < NN) {
        const float4* row4 = (const float4*)(xs + tid * DD);
        bool nz = false;
        #pragma unroll
        for (int e = 0; e < 8; e++) {
            float4 v = row4[e];
            nz = nz || (v.x != 0.f) || (v.y != 0.f) || (v.z != 0.f) || (v.w != 0.f);
        }
        maskS[tid] = nz ? 1.f : 0.f;
    }
    #pragma unroll
    for (int o = 16; o; o >>= 1) lsum += __shfl_xor_sync(0xffffffffu, lsum, o);
    if ((tid & 31) == 0) red[tid >> 5] = lsum;
    __syncthreads();
    const float denom = x_size[bm >> 3] * (float)DD;
    if (tid == 0) {
        float s = 0.f;
        #pragma unroll
        for (int w = 0; w < 8; w++) s += red[w];
        statS[0] = s / denom;
    }
    if (tid < 32) {
        int mx = -1;
        #pragma unroll
        for (int c = 0; c < 4; c++) {
            unsigned bal = __ballot_sync(0xffffffffu, maskS[c * 32 + tid] != 0.f);
            if (bal) { int hi = 31 - __clz((int)bal); if (c * 32 + hi > mx) mx = c * 32 + hi; }
        }
        if (tid == 0) g_nv[bm] = mx + 1;
    }
    __syncthreads();
    const float mean = statS[0];

    float lss = 0.f;
    #pragma unroll
    for (int i = tid; i < 1024; i += 256) {
        float4 v = xs4[i];
        float m = maskS[i >> 3];
        float a = v.x - mean, b = v.y - mean, c = v.z - mean, d = v.w - mean;
        lss += (a * a + b * b + c * c + d * d) * m;
    }
    #pragma unroll
    for (int o = 16; o; o >>= 1) lss += __shfl_xor_sync(0xffffffffu, lss, o);
    if ((tid & 31) == 0) red[tid >> 5] = lss;
    __syncthreads();
    if (tid == 0) {
        float s = 0.f;
        #pragma unroll
        for (int w = 0; w < 8; w++) s += red[w];
        statS[1] = 1.0f / (sqrtf(s / denom) + 1e-8f);
    }
    __syncthreads();
    const float inv = statS[1];

    #pragma unroll
    for (int i = tid; i < 512; i += 256) {
        int n = r0 + (i >> 5);
        int e = i & 31;
        xn[i] = (xs[n * DD + e] - mean) * inv * maskS[n];
    }
    if (tid < 16) g_mask[bm * NN + r0 + tid] = maskS[r0 + tid];
    __syncthreads();

    float* hb  = xs;          // 16*64
    float* x1b = xs + 1024;   // 16*32
    const int n  = tid >> 4;      // 0..15 (local row)
    const int kq = tid & 15;      // quad index

    {
        const float4* w1a4 = (const float4*)w1a;
        float4 acc = ((const float4*)b1a)[kq];
        const float* xr = xn + n * DD;
        #pragma unroll
        for (int e = 0; e < DD; e++) {
            float xv  = xr[e];
            float4 w  = w1a4[e * 16 + kq];
            acc.x = fmaf(xv, w.x, acc.x);
            acc.y = fmaf(xv, w.y, acc.y);
            acc.z = fmaf(xv, w.z, acc.z);
            acc.w = fmaf(xv, w.w, acc.w);
        }
        float4 g;
        g.x = gelu_f(acc.x); g.y = gelu_f(acc.y);
        g.z = gelu_f(acc.z); g.w = gelu_f(acc.w);
        ((float4*)hb)[n * 16 + kq] = g;
    }
    __syncthreads();

    {
        const float2* w1b2 = (const float2*)w1b;
        float2 acc = ((const float2*)b1b)[kq];
        const float* hr = hb + n * DD2;
        #pragma unroll
        for (int k = 0; k < DD2; k++) {
            float h  = hr[k];
            float2 w = w1b2[k * 16 + kq];
            acc.x = fmaf(h, w.x, acc.x);
            acc.y = fmaf(h, w.y, acc.y);
        }
        float m = maskS[r0 + n];
        acc.x *= m; acc.y *= m;
        ((float2*)x1b)[n * 16 + kq] = acc;
        *(float2*)(g_x1 + bm * (NN * DD) + (r0 + n) * DD + kq * 2) = acc;
    }
    __syncthreads();

    {
        const float4* w2a4 = (const float4*)w2a;
        float4 a1 = make_float4(0.f, 0.f, 0.f, 0.f);
        float4 a2 = make_float4(0.f, 0.f, 0.f, 0.f);
        const float* x1r = x1b + n * DD;
        const float* xnr = xn  + n * DD;
        #pragma unroll
        for (int e = 0; e < DD; e++) {
            float xa = x1r[e];
            float xb = xnr[e];
            float4 w = w2a4[e * 16 + kq];
            a1.x = fmaf(xa, w.x, a1.x); a1.y = fmaf(xa, w.y, a1.y);
            a1.z = fmaf(xa, w.z, a1.z); a1.w = fmaf(xa, w.w, a1.w);
            a2.x = fmaf(xb, w.x, a2.x); a2.y = fmaf(xb, w.y, a2.y);
            a2.z = fmaf(xb, w.z, a2.z); a2.w = fmaf(xb, w.w, a2.w);
        }
        const int go = bm * (NN * DD2) + (r0 + n) * DD2 + kq * 4;
        *(float4*)(g_A1 + go) = a1;
        *(float4*)(g_A2 + go) = a2;
    }
}

// ---------------------------------------------------------------------------
// Kernel 2: pair scores + aggregation. grid = NSET * 16 (one set x 8 j's),
// 512 threads, __launch_bounds__(512,3) -> 48 warps/SM when resident.
// Thread owns j = tid&7 and 2 i's (bi, bi+64); bi = tid>>3 in 0..63.
// ---------------------------------------------------------------------------
__global__ __launch_bounds__(512, 3) void k2(
    const float* __restrict__ x,
    const float* __restrict__ b2a, const float* __restrict__ W2b,
    const float* __restrict__ b2b, const float* __restrict__ w3,
    const float* __restrict__ b3, float* __restrict__ out)
{
    __shared__ float A1s[NN * A1S_STRIDE4 * 4];   // padded rows; reused as x1s later
    __shared__ float dS[8 * DS_STRIDE];
    __shared__ float vS[DD2];
    __shared__ float sS[NN * 8];
    __shared__ float PS[NN];
    __shared__ float QS[8];
    __shared__ float part[512];
    __shared__ float cS;

    const int bm = blockIdx.x >> 4;
    const int jt = blockIdx.x & 15;
    const int j0 = jt * 8;
    const int tid = threadIdx.x;

    const int Nv = g_nv[bm];
    if (j0 >= Nv) {     // fully masked: 8j x 32d = 64 float4 of zeros
        if (tid < 64)
            ((float4*)(out + bm * (NN * DD) + j0 * DD))[tid] = make_float4(0.f, 0.f, 0.f, 0.f);
        return;
    }
    const bool g1 = (Nv > 64);                          // second i-group live?
    const int nr   = min(4, max(2, (Nv + 31) >> 5));
    const int aggN = nr * 32;

    // --- stage A1 (padded rows; only valid-rounded rows), dS, half-v, c ---
    const float4* a1g  = (const float4*)(g_A1 + bm * (NN * DD2));
    float4*       A1s4 = (float4*)A1s;
    const int stage4 = g1 ? 2048 : 1024;
    for (int idx = tid; idx < stage4; idx += 512) {
        int i  = idx >> 4;
        int k4 = idx & 15;
        A1s4[i * A1S_STRIDE4 + k4] = a1g[idx];
    }
    {   // 512 entries: 8 j-rows x 64 k
        int jj = tid >> 6, k = tid & 63;
        dS[jj * DS_STRIDE + k] = b2a[k] - g_A2[bm * (NN * DD2) + (j0 + jj) * DD2 + k];
    }
    if (tid >= 448) {   // 64 threads: half-v
        int kk = tid - 448;
        float acc = 0.f;
        #pragma unroll
        for (int h = 0; h < 64; h++) acc = fmaf(W2b[kk * 64 + h], w3[h], acc);
        vS[kk] = 0.5f * acc;
    }
    if (tid == 0) {
        float acc = 0.f;
        #pragma unroll
        for (int h = 0; h < 64; h++) acc = fmaf(b2b[h], w3[h], acc);
        cS = acc;
    }
    __syncthreads();

    // --- P[i] and Q[j]; vS holds 0.5*v ---
    if (tid < NN) {
        const float* row = A1s + tid * (A1S_STRIDE4 * 4);
        float acc = 0.f;
        #pragma unroll
        for (int k = 0; k < DD2; k++) acc = fmaf(row[k], vS[k], acc);
        PS[tid] = acc;
    } else if (tid < NN + 8) {
        int jj = tid - NN;
        const float* row = dS + jj * DS_STRIDE;
        float acc = 0.f;
        #pragma unroll
        for (int k = 0; k < DD2; k++) acc = fmaf(row[k], vS[k], acc);
        QS[jj] = acc;
    }
    __syncthreads();

    // --- pair phase: thread owns j = tid&7 and i in {bi, bi+64} ---
    const int j  = tid & 7;
    const int bi = tid >> 3;     // 0..63
    const ulonglong2* A1s2 = (const ulonglong2*)A1s;
    const ulonglong2* dj2  = (const ulonglong2*)(dS + j * DS_STRIDE);
    const ulonglong2* vv2  = (const ulonglong2*)vS;

    const u64 C1 = f2pack(0.0356774081f, 0.0356774081f);
    const u64 C2 = f2pack(0.7978845608f, 0.7978845608f);

    float acc0 = 0.f, acc1 = 0.f;
    if (g1) {
        #pragma unroll
        for (int k4 = 0; k4 < 16; k4++) {
            ulonglong2 dd = dj2[k4];
            ulonglong2 hv = vv2[k4];
            ulonglong2 q0 = A1s2[(bi     ) * A1S_STRIDE4 + k4];
            ulonglong2 q1 = A1s2[(bi + 64) * A1S_STRIDE4 + k4];
            gelu2_nl1(q0.x, dd.x, hv.x, acc0, C1, C2);
            gelu2_nl1(q0.y, dd.y, hv.y, acc0, C1, C2);
            gelu2_nl1(q1.x, dd.x, hv.x, acc1, C1, C2);
            gelu2_nl1(q1.y, dd.y, hv.y, acc1, C1, C2);
        }
    } else {
        #pragma unroll
        for (int k4 = 0; k4 < 16; k4++) {
            ulonglong2 dd = dj2[k4];
            ulonglong2 hv = vv2[k4];
            ulonglong2 q0 = A1s2[(bi     ) * A1S_STRIDE4 + k4];
            gelu2_nl1(q0.x, dd.x, hv.x, acc0, C1, C2);
            gelu2_nl1(q0.y, dd.y, hv.y, acc0, C1, C2);
        }
    }
    {
        const float base = cS + QS[j];
        sS[(bi     ) * 8 + j] = base + PS[bi     ] + acc0;
        if (g1) sS[(bi + 64) * 8 + j] = base + PS[bi + 64] + acc1;
    }
    __syncthreads();

    // --- stage x1 into smem (reuse A1s region; pair phase done) ---
    float* x1s = A1s;
    {
        const float4* x1g4 = (const float4*)(g_x1 + bm * (NN * DD));
        #pragma unroll
        for (int idx = tid; idx < 1024; idx += 512) ((float4*)x1s)[idx] = x1g4[idx];
    }
    __syncthreads();

    // --- aggregation: 2 threads per (j,d), one per i-half ---
    {
        const int jd   = tid & 255;
        const int half = tid >> 8;
        const int jj   = jd >> 5;      // 0..7
        const int d    = jd & 31;
        const int ib   = half * 64;
        const int ie   = min(aggN, ib + 64);
        const float* sp = sS + jj;
        float acc = 0.f;
        #pragma unroll 4
        for (int i = ib; i < ie; i++) acc = fmaf(sp[i * 8], x1s[i * DD + d], acc);
        part[tid] = acc;
    }
    __syncthreads();
    if (tid < 256) {
        const int jj = tid >> 5;
        const int d  = tid & 31;
        const int gj = j0 + jj;
        const int gidx = bm * (NN * DD) + gj * DD + d;
        float r = part[tid] + part[tid + 256];
        out[gidx] = (r + b3[0] + x[gidx]) * g_mask[bm * NN + gj];
    }
}

// ---------------------------------------------------------------------------
extern "C" void kernel_launch(void* const* d_in, const int* in_sizes, int n_in,
                              void* d_out, int out_size)
{
    (void)in_sizes; (void)n_in; (void)out_size;
    const float* x    = (const float*)d_in[0];
    const float* xsz  = (const float*)d_in[1];
    const float* W1a  = (const float*)d_in[2];
    const float* b1a  = (const float*)d_in[3];
    const float* W1b  = (const float*)d_in[4];
    const float* b1b  = (const float*)d_in[5];
    const float* W2a  = (const float*)d_in[6];
    const float* b2a  = (const float*)d_in[7];
    const float* W2b  = (const float*)d_in[8];
    const float* b2b  = (const float*)d_in[9];
    const float* w3   = (const float*)d_in[10];
    const float* b3   = (const float*)d_in[11];
    float* out = (float*)d_out;

    k1<<<NSET * 8, 256>>>(x, xsz, W1a, b1a, W1b, b1b, W2a);
    k2<<<NSET * 16, 512>>>(x, b2a, W2b, b2b, w3, b3, out);
}